// round 2
// baseline (speedup 1.0000x reference)
#include <cuda_runtime.h>
#include <math.h>

#define NQ 14
#define NSTATE (1 << NQ)          // 16384 amplitudes
#define THREADS 256
#define QUADS (NSTATE / 4)        // 4096
#define QPT (QUADS / THREADS)     // 16 quads per thread per pass
#define APT (NSTATE / THREADS)    // 64 amps per thread (init)

struct SmallSmem {
    float2 u[NQ][2];              // per-qubit initial 2-vectors (RY embed * layer0 RX on |0>)
    float2 Tlow[64];              // product table, qubits 0..5
    float2 Thigh[256];            // product table, qubits 6..13
    float wc[2][NQ];              // cos(w/2) for layers 1,2
    float ws[2][NQ];              // sin(w/2) for layers 1,2
    unsigned int dmask[2][NQ];    // columns of M_l^{-1} (pair offsets), l=1,2
    unsigned int mmask[2][NQ];    // rows of M_l (parity masks), l=1,2
    unsigned int ro[NQ];          // rows of M_3 (readout Z-sign masks)
    float red[8][NQ];             // per-warp reduction buffer
};

__device__ __forceinline__ float2 cmulf(float2 a, float2 b) {
    return make_float2(a.x * b.x - a.y * b.y, a.x * b.y + a.y * b.x);
}

__global__ __launch_bounds__(THREADS, 1)
void qsim_kernel(const float* __restrict__ xin,
                 const float* __restrict__ win,
                 float* __restrict__ out)
{
    extern __shared__ float2 S[];           // 16384 complex amplitudes (131072 B)
    __shared__ SmallSmem sm;

    const int tid = threadIdx.x;
    const int samp = blockIdx.x;

    // ---------------- setup: per-qubit initial vectors u_q ----------------
    // u_q = RX(w0q) * RY(theta_q) |0>,  theta_q = tanh(x)*pi
    if (tid < NQ) {
        float th = tanhf(xin[samp * NQ + tid]) * 1.57079632679489662f; // tanh(x)*pi/2
        float c, s;
        sincosf(th, &s, &c);
        float hw = win[tid] * 0.5f;
        float sw, cw;
        sincosf(hw, &sw, &cw);
        // RX * (c, s)^T = (cw*c - i*sw*s,  cw*s - i*sw*c)
        sm.u[tid][0] = make_float2(cw * c, -sw * s);
        sm.u[tid][1] = make_float2(cw * s, -sw * c);
    }
    // layer 1,2 RX angle tables
    if (tid >= 64 && tid < 64 + 2 * NQ) {
        int l = (tid - 64) / NQ, q = (tid - 64) % NQ;
        float hw = win[(l + 1) * NQ + q] * 0.5f;
        float sw, cw;
        sincosf(hw, &sw, &cw);
        sm.wc[l][q] = cw;
        sm.ws[l][q] = sw;
    }
    // GF(2) bookkeeping for the CNOT rings: M_l = L^l rows, M_l^{-1} columns
    if (tid == 0) {
        unsigned row[NQ], col[NQ];
        for (int q = 0; q < NQ; q++) { row[q] = 1u << q; col[q] = 1u << q; }
        for (int step = 1; step <= 3; ++step) {
            unsigned nr[NQ], nc[NQ];
            unsigned all = 0;
            for (int q = 0; q < NQ; q++) all ^= row[q];
            nr[0] = all ^ row[0];                 // row0(L) = {1..13}
            unsigned pref = row[0];
            for (int k = 1; k < NQ; k++) { pref ^= row[k]; nr[k] = pref; } // rowk(L)={0..k}
            nc[0] = col[0] ^ col[1];              // col0(L^-1) = {0,1}
            for (int q = 1; q < NQ - 1; q++) nc[q] = col[q] ^ col[q + 1]; // {q,q+1}
            nc[NQ - 1] = col[0] ^ col[1] ^ col[NQ - 1];                   // {0,1,13}
            for (int q = 0; q < NQ; q++) { row[q] = nr[q]; col[q] = nc[q]; }
            if (step < 3) {
                for (int q = 0; q < NQ; q++) {
                    sm.dmask[step - 1][q] = col[q];
                    sm.mmask[step - 1][q] = row[q];
                }
            } else {
                for (int q = 0; q < NQ; q++) sm.ro[q] = row[q];
            }
        }
    }
    __syncthreads();

    // ---------------- product tables ----------------
    if (tid < 64) {
        float2 v = sm.u[0][tid & 1];
#pragma unroll
        for (int q = 1; q < 6; q++) v = cmulf(v, sm.u[q][(tid >> q) & 1]);
        sm.Tlow[tid] = v;
    }
    {
        float2 v = sm.u[6][tid & 1];
#pragma unroll
        for (int q = 1; q < 8; q++) v = cmulf(v, sm.u[6 + q][(tid >> q) & 1]);
        sm.Thigh[tid] = v;
    }
    __syncthreads();

    // ---------------- init: write post-layer-0 product state ----------------
#pragma unroll
    for (int k = 0; k < APT; k++) {
        int p = k * THREADS + tid;
        S[p] = cmulf(sm.Tlow[p & 63], sm.Thigh[p >> 6]);
    }

    float acc[NQ];
#pragma unroll
    for (int q = 0; q < NQ; q++) acc[q] = 0.0f;

    // ---------------- layers 1 and 2: fused 2-qubit RX passes ----------------
    for (int l = 0; l < 2; l++) {
        for (int pass = 0; pass < 7; ++pass) {
            const int q0 = pass;       // pair (q, q+7): spreads low/high bit masks
            const int q1 = pass + 7;
            const unsigned d0 = sm.dmask[l][q0], d1 = sm.dmask[l][q1];
            const unsigned m0 = sm.mmask[l][q0], m1 = sm.mmask[l][q1];
            const float c0 = sm.wc[l][q0], s0 = sm.ws[l][q0];
            const float c1 = sm.wc[l][q1], s1 = sm.ws[l][q1];

            // pivot bits for coset enumeration
            const int j0 = __ffs((int)d0) - 1;
            const unsigned d1p = ((d1 >> j0) & 1u) ? (d1 ^ d0) : d1;
            const int j1 = __ffs((int)d1p) - 1;
            const int ja = j0 < j1 ? j0 : j1;
            const int jb = j0 < j1 ? j1 : j0;

            const bool last = (l == 1) && (pass == 6);
            unsigned f0bits = 0, f1bits = 0;
            if (last) {
#pragma unroll
                for (int q = 0; q < NQ; q++) {
                    f0bits |= (unsigned)(__popc(sm.ro[q] & d0) & 1) << q;
                    f1bits |= (unsigned)(__popc(sm.ro[q] & d1) & 1) << q;
                }
            }

            __syncthreads();   // previous pass stores -> this pass loads

#pragma unroll
            for (int k = 0; k < QPT; k++) {
                unsigned t = (unsigned)(k * THREADS + tid);      // 12-bit coset id
                unsigned low = t & ((1u << ja) - 1u);
                unsigned mid = (t >> ja) & ((1u << (jb - 1 - ja)) - 1u);
                unsigned high = t >> (jb - 1);
                unsigned z = low | (mid << (ja + 1)) | (high << (jb + 1));
                unsigned p00 = z;
                if (__popc(m0 & z) & 1) p00 ^= d0;   // force logical bit q0 = 0
                if (__popc(m1 & z) & 1) p00 ^= d1;   // force logical bit q1 = 0 (m1&d0==0)
                unsigned p10 = p00 ^ d0;
                unsigned p01 = p00 ^ d1;
                unsigned p11 = p10 ^ d1;

                float2 a00 = S[p00], a10 = S[p10], a01 = S[p01], a11 = S[p11];

                // RX(q0): mixes (a00,a10) and (a01,a11).  RX = [[c,-is],[-is,c]]
                float2 n00, n10, n01, n11;
                n00.x = c0 * a00.x + s0 * a10.y;  n00.y = c0 * a00.y - s0 * a10.x;
                n10.x = s0 * a00.y + c0 * a10.x;  n10.y = -s0 * a00.x + c0 * a10.y;
                n01.x = c0 * a01.x + s0 * a11.y;  n01.y = c0 * a01.y - s0 * a11.x;
                n11.x = s0 * a01.y + c0 * a11.x;  n11.y = -s0 * a01.x + c0 * a11.y;

                // RX(q1): mixes (n00,n01) and (n10,n11)
                a00.x = c1 * n00.x + s1 * n01.y;  a00.y = c1 * n00.y - s1 * n01.x;
                a01.x = s1 * n00.y + c1 * n01.x;  a01.y = -s1 * n00.x + c1 * n01.y;
                a10.x = c1 * n10.x + s1 * n11.y;  a10.y = c1 * n10.y - s1 * n11.x;
                a11.x = s1 * n10.y + c1 * n11.x;  a11.y = -s1 * n10.x + c1 * n11.y;

                S[p00] = a00; S[p10] = a10; S[p01] = a01; S[p11] = a11;

                if (last) {
                    // fold readout: contribution of this quad to all 14 <Z_q>
                    float pr00 = a00.x * a00.x + a00.y * a00.y;
                    float pr10 = a10.x * a10.x + a10.y * a10.y;
                    float pr01 = a01.x * a01.x + a01.y * a01.y;
                    float pr11 = a11.x * a11.x + a11.y * a11.y;
                    float c0p = pr00 + pr10, c0m = pr00 - pr10;
                    float c1p = pr01 + pr11, c1m = pr01 - pr11;
                    float cb00 = c0p + c1p;   // (f0,f1)=(0,0)
                    float cb10 = c0m + c1m;   // (1,0)
                    float cb01 = c0p - c1p;   // (0,1)
                    float cb11 = c0m - c1m;   // (1,1)
#pragma unroll
                    for (int q = 0; q < NQ; q++) {
                        float v = ((f1bits >> q) & 1u)
                                      ? (((f0bits >> q) & 1u) ? cb11 : cb01)
                                      : (((f0bits >> q) & 1u) ? cb10 : cb00);
                        if (__popc(sm.ro[q] & p00) & 1) v = -v;
                        acc[q] += v;
                    }
                }
            }
        }
    }

    // ---------------- block reduction of <Z_q> ----------------
#pragma unroll
    for (int q = 0; q < NQ; q++) {
#pragma unroll
        for (int off = 16; off; off >>= 1)
            acc[q] += __shfl_xor_sync(0xffffffffu, acc[q], off);
    }
    const int wid = tid >> 5, lane = tid & 31;
    if (lane == 0) {
#pragma unroll
        for (int q = 0; q < NQ; q++) sm.red[wid][q] = acc[q];
    }
    __syncthreads();
    if (tid < NQ) {
        float r = 0.0f;
#pragma unroll
        for (int w = 0; w < 8; w++) r += sm.red[w][tid];
        out[samp * NQ + tid] = r;
    }
}

extern "C" void kernel_launch(void* const* d_in, const int* in_sizes, int n_in,
                              void* d_out, int out_size)
{
    const float* x = (const float*)d_in[0];
    const float* w = (const float*)d_in[1];
    if (n_in >= 2 && in_sizes[0] == 3 * NQ && in_sizes[1] != 3 * NQ) {
        // defensive: inputs arrived as (weights, x)
        const float* tmp = x; x = w; w = tmp;
    }
    const int batch = out_size / NQ;

    cudaFuncSetAttribute(qsim_kernel,
                         cudaFuncAttributeMaxDynamicSharedMemorySize,
                         NSTATE * (int)sizeof(float2));

    qsim_kernel<<<batch, THREADS, NSTATE * sizeof(float2)>>>(x, w, (float*)d_out);
}

// round 4
// speedup vs baseline: 1.1621x; 1.1621x over previous
#include <cuda_runtime.h>
#include <math.h>

#define NQ 14
#define NSTATE (1 << NQ)          // 16384 amplitudes
#define THREADS 512
#define NWARP (THREADS / 32)
#define QUADS (NSTATE / 4)        // 4096
#define QPT (QUADS / THREADS)     // 8 quads per thread per pass
#define APT (NSTATE / THREADS)    // 32 amps per thread (init)

struct SmallSmem {
    float2 u[NQ][2];              // per-qubit initial 2-vectors (RY embed * layer0 RX on |0>)
    float2 Tlow[64];              // product table, qubits 0..5
    float2 Thigh[256];            // product table, qubits 6..13
    float wc[2][NQ];              // cos(w/2) for layers 1,2
    float ws[2][NQ];              // sin(w/2) for layers 1,2
    unsigned int dmask[2][NQ];    // columns of M_l^{-1} (pair offsets), l=1,2
    unsigned int mmask[2][NQ];    // rows of M_l (parity masks), l=1,2
    unsigned int ro[NQ];          // rows of M_3 (readout Z-sign masks)
    float red[NWARP][NQ];         // per-warp reduction buffer
};

__device__ __forceinline__ float2 cmulf(float2 a, float2 b) {
    return make_float2(a.x * b.x - a.y * b.y, a.x * b.y + a.y * b.x);
}

__global__ __launch_bounds__(THREADS, 1)
void qsim_kernel(const float* __restrict__ xin,
                 const float* __restrict__ win,
                 float* __restrict__ out)
{
    extern __shared__ float2 S[];           // 16384 complex amplitudes (131072 B)
    __shared__ SmallSmem sm;

    const int tid = threadIdx.x;
    const int samp = blockIdx.x;

    // ---------------- setup: per-qubit initial vectors u_q ----------------
    // u_q = RX(w0q) * RY(theta_q) |0>,  theta_q = tanh(x)*pi
    if (tid < NQ) {
        float th = tanhf(xin[samp * NQ + tid]) * 1.57079632679489662f; // tanh(x)*pi/2
        float c, s;
        sincosf(th, &s, &c);
        float hw = win[tid] * 0.5f;
        float sw, cw;
        sincosf(hw, &sw, &cw);
        // RX * (c, s)^T = (cw*c - i*sw*s,  cw*s - i*sw*c)
        sm.u[tid][0] = make_float2(cw * c, -sw * s);
        sm.u[tid][1] = make_float2(cw * s, -sw * c);
    }
    // layer 1,2 RX angle tables
    if (tid >= 64 && tid < 64 + 2 * NQ) {
        int l = (tid - 64) / NQ, q = (tid - 64) % NQ;
        float hw = win[(l + 1) * NQ + q] * 0.5f;
        float sw, cw;
        sincosf(hw, &sw, &cw);
        sm.wc[l][q] = cw;
        sm.ws[l][q] = sw;
    }
    // GF(2) bookkeeping for the CNOT rings: M_l = L^l rows, M_l^{-1} columns
    if (tid == 0) {
        unsigned row[NQ], col[NQ];
        for (int q = 0; q < NQ; q++) { row[q] = 1u << q; col[q] = 1u << q; }
        for (int step = 1; step <= 3; ++step) {
            unsigned nr[NQ], nc[NQ];
            unsigned all = 0;
            for (int q = 0; q < NQ; q++) all ^= row[q];
            nr[0] = all ^ row[0];                 // row0(L) = {1..13}
            unsigned pref = row[0];
            for (int k = 1; k < NQ; k++) { pref ^= row[k]; nr[k] = pref; } // rowk(L)={0..k}
            nc[0] = col[0] ^ col[1];              // col0(L^-1) = {0,1}
            for (int q = 1; q < NQ - 1; q++) nc[q] = col[q] ^ col[q + 1]; // {q,q+1}
            nc[NQ - 1] = col[0] ^ col[1] ^ col[NQ - 1];                   // {0,1,13}
            for (int q = 0; q < NQ; q++) { row[q] = nr[q]; col[q] = nc[q]; }
            if (step < 3) {
                for (int q = 0; q < NQ; q++) {
                    sm.dmask[step - 1][q] = col[q];
                    sm.mmask[step - 1][q] = row[q];
                }
            } else {
                for (int q = 0; q < NQ; q++) sm.ro[q] = row[q];
            }
        }
    }
    __syncthreads();

    // ---------------- product tables ----------------
    if (tid < 64) {
        float2 v = sm.u[0][tid & 1];
#pragma unroll
        for (int q = 1; q < 6; q++) v = cmulf(v, sm.u[q][(tid >> q) & 1]);
        sm.Tlow[tid] = v;
    }
    if (tid < 256) {
        float2 v = sm.u[6][tid & 1];
#pragma unroll
        for (int q = 1; q < 8; q++) v = cmulf(v, sm.u[6 + q][(tid >> q) & 1]);
        sm.Thigh[tid] = v;
    }
    __syncthreads();

    // ---------------- init: write post-layer-0 product state ----------------
#pragma unroll
    for (int k = 0; k < APT; k++) {
        int p = k * THREADS + tid;
        S[p] = cmulf(sm.Tlow[p & 63], sm.Thigh[p >> 6]);
    }

    float acc[NQ];
#pragma unroll
    for (int q = 0; q < NQ; q++) acc[q] = 0.0f;

    // ---------------- layers 1 and 2: fused 2-qubit RX passes ----------------
    for (int l = 0; l < 2; l++) {
        for (int pass = 0; pass < 7; ++pass) {
            const int q0 = pass;       // pair (q, q+7): spreads low/high bit masks
            const int q1 = pass + 7;
            const unsigned d0 = sm.dmask[l][q0], d1 = sm.dmask[l][q1];
            const unsigned m0 = sm.mmask[l][q0], m1 = sm.mmask[l][q1];
            const float c0 = sm.wc[l][q0], s0 = sm.ws[l][q0];
            const float c1 = sm.wc[l][q1], s1 = sm.ws[l][q1];

            // pivot bits (removed from enumeration space)
            const int j0 = __ffs((int)d0) - 1;
            const unsigned d1p = ((d1 >> j0) & 1u) ? (d1 ^ d0) : d1;
            const int j1 = __ffs((int)d1p) - 1;
            const int ja = j0 < j1 ? j0 : j1;
            const int jb = j0 < j1 ? j1 : j0;

            // The coset-representative map t -> p00 is GF(2)-LINEAR:
            //   p00(z) = z ^ parity(m0&z)*d0 ^ parity(m1&z)*d1, z(t) = bit-insert.
            // Build its 12-vector basis once per pass; per-quad addressing is XOR only.
            unsigned basis[12];
            {
                int idx = 0;
                for (int b = 0; b < NQ; b++) {
                    if (b == ja || b == jb) continue;
                    unsigned z = 1u << b;
                    unsigned p = z;
                    if (__popc(m0 & z) & 1) p ^= d0;
                    if (__popc(m1 & z) & 1) p ^= d1;
                    basis[idx++] = p;
                }
            }
            unsigned pbase = 0;
#pragma unroll
            for (int j = 0; j < 9; j++)
                if ((tid >> j) & 1) pbase ^= basis[j];

            const bool last = (l == 1) && (pass == 6);
            unsigned f0bits = 0, f1bits = 0;
            if (last) {
#pragma unroll
                for (int q = 0; q < NQ; q++) {
                    f0bits |= (unsigned)(__popc(sm.ro[q] & d0) & 1) << q;
                    f1bits |= (unsigned)(__popc(sm.ro[q] & d1) & 1) << q;
                }
            }

            __syncthreads();   // previous pass stores -> this pass loads

#pragma unroll
            for (int k = 0; k < QPT; k++) {
                unsigned p00 = pbase;
                if (k & 1) p00 ^= basis[9];
                if (k & 2) p00 ^= basis[10];
                if (k & 4) p00 ^= basis[11];
                unsigned p10 = p00 ^ d0;
                unsigned p01 = p00 ^ d1;
                unsigned p11 = p10 ^ d1;

                float2 a00 = S[p00], a10 = S[p10], a01 = S[p01], a11 = S[p11];

                // RX(q0): mixes (a00,a10) and (a01,a11).  RX = [[c,-is],[-is,c]]
                float2 n00, n10, n01, n11;
                n00.x = c0 * a00.x + s0 * a10.y;  n00.y = c0 * a00.y - s0 * a10.x;
                n10.x = s0 * a00.y + c0 * a10.x;  n10.y = -s0 * a00.x + c0 * a10.y;
                n01.x = c0 * a01.x + s0 * a11.y;  n01.y = c0 * a01.y - s0 * a11.x;
                n11.x = s0 * a01.y + c0 * a11.x;  n11.y = -s0 * a01.x + c0 * a11.y;

                // RX(q1): mixes (n00,n01) and (n10,n11)
                a00.x = c1 * n00.x + s1 * n01.y;  a00.y = c1 * n00.y - s1 * n01.x;
                a01.x = s1 * n00.y + c1 * n01.x;  a01.y = -s1 * n00.x + c1 * n01.y;
                a10.x = c1 * n10.x + s1 * n11.y;  a10.y = c1 * n10.y - s1 * n11.x;
                a11.x = s1 * n10.y + c1 * n11.x;  a11.y = -s1 * n10.x + c1 * n11.y;

                S[p00] = a00; S[p10] = a10; S[p01] = a01; S[p11] = a11;

                if (last) {
                    // fold readout: contribution of this quad to all 14 <Z_q>
                    float pr00 = a00.x * a00.x + a00.y * a00.y;
                    float pr10 = a10.x * a10.x + a10.y * a10.y;
                    float pr01 = a01.x * a01.x + a01.y * a01.y;
                    float pr11 = a11.x * a11.x + a11.y * a11.y;
                    float c0p = pr00 + pr10, c0m = pr00 - pr10;
                    float c1p = pr01 + pr11, c1m = pr01 - pr11;
                    float cb00 = c0p + c1p;   // (f0,f1)=(0,0)
                    float cb10 = c0m + c1m;   // (1,0)
                    float cb01 = c0p - c1p;   // (0,1)
                    float cb11 = c0m - c1m;   // (1,1)
#pragma unroll
                    for (int q = 0; q < NQ; q++) {
                        float v = ((f1bits >> q) & 1u)
                                      ? (((f0bits >> q) & 1u) ? cb11 : cb01)
                                      : (((f0bits >> q) & 1u) ? cb10 : cb00);
                        if (__popc(sm.ro[q] & p00) & 1) v = -v;
                        acc[q] += v;
                    }
                }
            }
        }
    }

    // ---------------- block reduction of <Z_q> ----------------
#pragma unroll
    for (int q = 0; q < NQ; q++) {
#pragma unroll
        for (int off = 16; off; off >>= 1)
            acc[q] += __shfl_xor_sync(0xffffffffu, acc[q], off);
    }
    const int wid = tid >> 5, lane = tid & 31;
    if (lane == 0) {
#pragma unroll
        for (int q = 0; q < NQ; q++) sm.red[wid][q] = acc[q];
    }
    __syncthreads();
    if (tid < NQ) {
        float r = 0.0f;
#pragma unroll
        for (int w = 0; w < NWARP; w++) r += sm.red[w][tid];
        out[samp * NQ + tid] = r;
    }
}

extern "C" void kernel_launch(void* const* d_in, const int* in_sizes, int n_in,
                              void* d_out, int out_size)
{
    const float* x = (const float*)d_in[0];
    const float* w = (const float*)d_in[1];
    if (n_in >= 2 && in_sizes[0] == 3 * NQ && in_sizes[1] != 3 * NQ) {
        // defensive: inputs arrived as (weights, x)
        const float* tmp = x; x = w; w = tmp;
    }
    const int batch = out_size / NQ;

    cudaFuncSetAttribute(qsim_kernel,
                         cudaFuncAttributeMaxDynamicSharedMemorySize,
                         NSTATE * (int)sizeof(float2));

    qsim_kernel<<<batch, THREADS, NSTATE * sizeof(float2)>>>(x, w, (float*)d_out);
}

// round 7
// speedup vs baseline: 1.8943x; 1.6301x over previous
#include <cuda_runtime.h>
#include <math.h>

#define NQ 14
#define NSTATE (1 << NQ)          // 16384 amplitudes
#define THREADS 512
#define NWARP (THREADS / 32)
#define NPASS 8

// qubit r of group g: q = g + 4*r  (g=0,1 -> 4 qubits; g=2,3 -> 3 qubits)
#define GNQ(g) ((g) < 2 ? 4 : 3)

struct SmallSmem {
    float2 u[NQ][2];              // per-qubit initial 2-vectors (RY embed * layer0 RX on |0>)
    float2 Tlow[64];              // product table, qubits 0..5
    float2 Thigh[256];            // product table, qubits 6..13
    float wc[2][NQ];              // cos(w/2) for layers 1,2
    float ws[2][NQ];              // sin(w/2) for layers 1,2
    unsigned dmask[2][NQ];        // columns of M_l^{-1} (pair offsets), l=1,2
    unsigned mmask[2][NQ];        // rows of M_l (parity masks), l=1,2
    unsigned ro[NQ];              // rows of M_3 (readout Z-sign masks)
    unsigned basisT[NPASS][11];   // per-pass coset-representative basis vectors
    unsigned rocode[NQ];          // 3-bit Walsh combo code per readout qubit (last pass)
    float red[NWARP][NQ];         // per-warp reduction buffer
};

__device__ __forceinline__ float2 cmulf(float2 a, float2 b) {
    return make_float2(a.x * b.x - a.y * b.y, a.x * b.y + a.y * b.x);
}

// One fused multi-qubit RX pass over the whole state.
// L: weight-layer index (0 => weights row 1, 1 => weights row 2)
// G: group index, qubits {G+4r}. NGQ in {3,4}. KG = groups per thread.
template<int L, int G, int NGQ, int KG, bool FIRST, bool LAST>
__device__ __forceinline__ void do_pass(float2* __restrict__ S, SmallSmem& sm,
                                        int tid, float* acc)
{
    constexpr int PI = L * 4 + G;
    constexpr int NM = 1 << NGQ;

    unsigned d[NGQ];
    float cs[NGQ], sn[NGQ];
#pragma unroll
    for (int r = 0; r < NGQ; r++) {
        int q = G + 4 * r;
        d[r]  = sm.dmask[L][q];
        cs[r] = sm.wc[L][q];
        sn[r] = sm.ws[L][q];
    }

    // subset-XOR offsets of the group members (compile-time structured)
    unsigned offs[NM];
    offs[0] = 0;
#pragma unroll
    for (int r = 0; r < NGQ; r++)
#pragma unroll
        for (int i = 0; i < NM; i++)
            if ((i >> r) == 1)                 // lowest set bit of i is r
                offs[i] = offs[i - (1 << r)] ^ d[r];

    // coset-representative base address for this thread (GF(2)-linear in tid)
    unsigned pb0 = 0;
#pragma unroll
    for (int j = 0; j < 9; j++)
        if ((tid >> j) & 1) pb0 ^= sm.basisT[PI][j];
    unsigned kb0 = sm.basisT[PI][9];
    unsigned kb1 = (KG > 2) ? sm.basisT[PI][10] : 0u;

    // readout constants (uniform), hoisted out of the k loop
    unsigned ro_r[LAST ? NQ : 1];
    unsigned code_r[LAST ? NQ : 1];
    if (LAST) {
#pragma unroll
        for (int q = 0; q < NQ; q++) { ro_r[q] = sm.ro[q]; code_r[q] = sm.rocode[q]; }
    }

    __syncthreads();   // previous pass stores -> this pass loads

#pragma unroll 1
    for (int k = 0; k < KG; k++) {
        unsigned pb = pb0;
        if (k & 1) pb ^= kb0;
        if (KG > 2 && (k & 2)) pb ^= kb1;

        float2 A[NM];
#pragma unroll
        for (int i = 0; i < NM; i++) {
            unsigned p = pb ^ offs[i];
            if (FIRST) A[i] = cmulf(sm.Tlow[p & 63], sm.Thigh[p >> 6]);
            else       A[i] = S[p];
        }

        // NGQ levels of RX butterflies: level r mixes (i, i|1<<r).
        // RX = [[c,-is],[-is,c]] (symmetric), logical bit r of member i is i_r.
#pragma unroll
        for (int r = 0; r < NGQ; r++) {
            float c = cs[r], s = sn[r];
#pragma unroll
            for (int i = 0; i < NM; i++) {
                if (i & (1 << r)) continue;
                int j = i | (1 << r);
                float2 a = A[i], b = A[j];
                A[i].x = c * a.x + s * b.y;  A[i].y = c * a.y - s * b.x;
                A[j].x = s * a.y + c * b.x;  A[j].y = -s * a.x + c * b.y;
            }
        }

#pragma unroll
        for (int i = 0; i < NM; i++) S[pb ^ offs[i]] = A[i];

        if (LAST) {
            // fold readout: Walsh transform of probabilities over the group,
            // then pick combo per qubit by its 3-bit code, sign by parity(ro&pb).
            float pr[NM];
#pragma unroll
            for (int i = 0; i < NM; i++) pr[i] = A[i].x * A[i].x + A[i].y * A[i].y;
#pragma unroll
            for (int r = 0; r < NGQ; r++) {
#pragma unroll
                for (int i = 0; i < NM; i++) {
                    if (i & (1 << r)) continue;
                    int j = i | (1 << r);
                    float u2 = pr[i], v2 = pr[j];
                    pr[i] = u2 + v2; pr[j] = u2 - v2;
                }
            }
#pragma unroll
            for (int q = 0; q < NQ; q++) {
                unsigned code = code_r[q];
                float t0 = (code & 1) ? pr[1] : pr[0];
                float t1 = (code & 1) ? pr[3] : pr[2];
                float t2 = (code & 1) ? pr[5] : pr[4];
                float t3 = (code & 1) ? pr[7] : pr[6];
                float u0 = (code & 2) ? t1 : t0;
                float u1 = (code & 2) ? t3 : t2;
                float v  = (code & 4) ? u1 : u0;
                unsigned sgn = (unsigned)(__popc(ro_r[q] & pb) & 1) << 31;
                acc[q] += __uint_as_float(__float_as_uint(v) ^ sgn);
            }
        }
    }
}

__global__ __launch_bounds__(THREADS, 1)
void qsim_kernel(const float* __restrict__ xin,
                 const float* __restrict__ win,
                 float* __restrict__ out)
{
    extern __shared__ float2 S[];           // 16384 complex amplitudes (131072 B)
    __shared__ SmallSmem sm;

    const int tid = threadIdx.x;
    const int samp = blockIdx.x;

    // ---------------- setup stage 1 ----------------
    if (tid < NQ) {
        float th = tanhf(xin[samp * NQ + tid]) * 1.57079632679489662f; // tanh(x)*pi/2
        float c, s;
        sincosf(th, &s, &c);
        float hw = win[tid] * 0.5f;
        float sw, cw;
        sincosf(hw, &sw, &cw);
        sm.u[tid][0] = make_float2(cw * c, -sw * s);
        sm.u[tid][1] = make_float2(cw * s, -sw * c);
    }
    if (tid >= 64 && tid < 64 + 2 * NQ) {
        int l = (tid - 64) / NQ, q = (tid - 64) % NQ;
        float hw = win[(l + 1) * NQ + q] * 0.5f;
        float sw, cw;
        sincosf(hw, &sw, &cw);
        sm.wc[l][q] = cw;
        sm.ws[l][q] = sw;
    }
    // GF(2) bookkeeping for the CNOT rings: M_l = L^l rows, M_l^{-1} columns
    if (tid == 0) {
        unsigned row[NQ], col[NQ];
        for (int q = 0; q < NQ; q++) { row[q] = 1u << q; col[q] = 1u << q; }
        for (int step = 1; step <= 3; ++step) {
            unsigned nr[NQ], nc[NQ];
            unsigned all = 0;
            for (int q = 0; q < NQ; q++) all ^= row[q];
            nr[0] = all ^ row[0];
            unsigned pref = row[0];
            for (int k = 1; k < NQ; k++) { pref ^= row[k]; nr[k] = pref; }
            nc[0] = col[0] ^ col[1];
            for (int q = 1; q < NQ - 1; q++) nc[q] = col[q] ^ col[q + 1];
            nc[NQ - 1] = col[0] ^ col[1] ^ col[NQ - 1];
            for (int q = 0; q < NQ; q++) { row[q] = nr[q]; col[q] = nc[q]; }
            if (step < 3) {
                for (int q = 0; q < NQ; q++) {
                    sm.dmask[step - 1][q] = col[q];
                    sm.mmask[step - 1][q] = row[q];
                }
            } else {
                for (int q = 0; q < NQ; q++) sm.ro[q] = row[q];
            }
        }
    }
    __syncthreads();

    // ---------------- setup stage 2: basis tables, readout codes, product tables ----
    if (tid < NPASS) {
        const int l = tid >> 2, g = tid & 3;
        const int ng = GNQ(g);
        unsigned d[4], m[4];
        for (int r = 0; r < ng; r++) {
            int q = g + 4 * r;
            d[r] = sm.dmask[l][q];
            m[r] = sm.mmask[l][q];
        }
        // pivots via Gaussian elimination (d's are linearly independent)
        unsigned red[4]; int piv[4];
        unsigned pivmask = 0;
        for (int r = 0; r < ng; r++) {
            unsigned v = d[r];
            for (int h = 0; h < r; h++)
                if ((v >> piv[h]) & 1u) v ^= red[h];
            piv[r] = __ffs((int)v) - 1;
            red[r] = v;
            pivmask |= 1u << piv[r];
        }
        // basis of the t -> p_base linear map (non-pivot index bits, low to high)
        int idx = 0;
        for (int b = 0; b < NQ; b++) {
            if ((pivmask >> b) & 1u) continue;
            unsigned p = 1u << b;
            for (int r = 0; r < ng; r++)
                if ((m[r] >> b) & 1u) p ^= d[r];
            sm.basisT[tid][idx++] = p;
        }
    }
    if (tid == 8) {
        // readout codes for the final pass (l=1, g=3, qubits {3,7,11})
        for (int q = 0; q < NQ; q++) {
            unsigned c = 0;
            for (int r = 0; r < 3; r++)
                c |= (unsigned)(__popc(sm.ro[q] & sm.dmask[1][3 + 4 * r]) & 1) << r;
            sm.rocode[q] = c;
        }
    }
    if (tid < 64) {
        float2 v = sm.u[0][tid & 1];
#pragma unroll
        for (int q = 1; q < 6; q++) v = cmulf(v, sm.u[q][(tid >> q) & 1]);
        sm.Tlow[tid] = v;
    }
    if (tid >= 128 && tid < 384) {
        int t = tid - 128;
        float2 v = sm.u[6][t & 1];
#pragma unroll
        for (int q = 1; q < 8; q++) v = cmulf(v, sm.u[6 + q][(t >> q) & 1]);
        sm.Thigh[t] = v;
    }
    __syncthreads();

    float acc[NQ];
#pragma unroll
    for (int q = 0; q < NQ; q++) acc[q] = 0.0f;

    // ---------------- 8 fused passes (layer 1, layer 2) ----------------
    do_pass<0, 0, 4, 2, true,  false>(S, sm, tid, acc);
    do_pass<0, 1, 4, 2, false, false>(S, sm, tid, acc);
    do_pass<0, 2, 3, 4, false, false>(S, sm, tid, acc);
    do_pass<0, 3, 3, 4, false, false>(S, sm, tid, acc);
    do_pass<1, 0, 4, 2, false, false>(S, sm, tid, acc);
    do_pass<1, 1, 4, 2, false, false>(S, sm, tid, acc);
    do_pass<1, 2, 3, 4, false, false>(S, sm, tid, acc);
    do_pass<1, 3, 3, 4, false, true >(S, sm, tid, acc);

    // ---------------- block reduction of <Z_q> ----------------
#pragma unroll
    for (int q = 0; q < NQ; q++) {
#pragma unroll
        for (int off = 16; off; off >>= 1)
            acc[q] += __shfl_xor_sync(0xffffffffu, acc[q], off);
    }
    const int wid = tid >> 5, lane = tid & 31;
    if (lane == 0) {
#pragma unroll
        for (int q = 0; q < NQ; q++) sm.red[wid][q] = acc[q];
    }
    __syncthreads();
    if (tid < NQ) {
        float r = 0.0f;
#pragma unroll
        for (int w = 0; w < NWARP; w++) r += sm.red[w][tid];
        out[samp * NQ + tid] = r;
    }
}

extern "C" void kernel_launch(void* const* d_in, const int* in_sizes, int n_in,
                              void* d_out, int out_size)
{
    const float* x = (const float*)d_in[0];
    const float* w = (const float*)d_in[1];
    if (n_in >= 2 && in_sizes[0] == 3 * NQ && in_sizes[1] != 3 * NQ) {
        // defensive: inputs arrived as (weights, x)
        const float* tmp = x; x = w; w = tmp;
    }
    const int batch = out_size / NQ;

    cudaFuncSetAttribute(qsim_kernel,
                         cudaFuncAttributeMaxDynamicSharedMemorySize,
                         NSTATE * (int)sizeof(float2));

    qsim_kernel<<<batch, THREADS, NSTATE * sizeof(float2)>>>(x, w, (float*)d_out);
}